// round 16
// baseline (speedup 1.0000x reference)
#include <cuda_runtime.h>
#include <cuda_fp16.h>

#define N_TOK 8192
#define EMB   1024
#define FFD   4096
#define SEQ   2048
#define NB    4
#define NH    16
#define HD    64

// ---------------- scratch ----------------
__device__ __half g_h  [N_TOK * EMB];
__device__ __half g_qkv[(size_t)N_TOK * 3 * EMB];
__device__ __half g_y  [N_TOK * EMB];
__device__ float  g_x2 [N_TOK * EMB];
__device__ __half g_ff [(size_t)N_TOK * FFD];
__device__ __half g_wqkv[3 * EMB * EMB];
__device__ __half g_wot [EMB * EMB];
__device__ __half g_w1t [(size_t)FFD * EMB];
__device__ __half g_w2t [(size_t)EMB * FFD];
__device__ float  g_bqkv[3 * EMB];

// fast exp on the FMA pipe
__device__ __forceinline__ float fexp(float x) {
    float t = fmaxf(x * 1.4426950408889634f, -126.0f);
    float fm = t + 12582912.0f;
    int   ib = __float_as_int(fm);
    float f  = t - (fm - 12582912.0f);
    float p = 1.33335581464284e-3f;
    p = fmaf(p, f, 9.61812910762848e-3f);
    p = fmaf(p, f, 5.55041086648216e-2f);
    p = fmaf(p, f, 2.40226506959101e-1f);
    p = fmaf(p, f, 6.93147180559945e-1f);
    p = fmaf(p, f, 1.0f);
    unsigned sc = ((unsigned)ib << 23) + 0x3f800000u;
    return p * __uint_as_float(sc);
}

__device__ __forceinline__ void ldsm4(unsigned& r0, unsigned& r1, unsigned& r2,
                                      unsigned& r3, unsigned addr) {
    asm volatile("ldmatrix.sync.aligned.m8n8.x4.shared.b16 {%0,%1,%2,%3}, [%4];\n"
                 : "=r"(r0), "=r"(r1), "=r"(r2), "=r"(r3) : "r"(addr));
}

__device__ __forceinline__ void ldsm4t(unsigned& r0, unsigned& r1, unsigned& r2,
                                       unsigned& r3, unsigned addr) {
    asm volatile("ldmatrix.sync.aligned.m8n8.x4.trans.shared.b16 {%0,%1,%2,%3}, [%4];\n"
                 : "=r"(r0), "=r"(r1), "=r"(r2), "=r"(r3) : "r"(addr));
}

__device__ __forceinline__ void mma_f16(float* d, const unsigned* a, const unsigned* b) {
    asm volatile(
        "mma.sync.aligned.m16n8k16.row.col.f32.f16.f16.f32 "
        "{%0,%1,%2,%3}, {%4,%5,%6,%7}, {%8,%9}, {%0,%1,%2,%3};\n"
        : "+f"(d[0]), "+f"(d[1]), "+f"(d[2]), "+f"(d[3])
        : "r"(a[0]), "r"(a[1]), "r"(a[2]), "r"(a[3]), "r"(b[0]), "r"(b[1]));
}

__device__ __forceinline__ unsigned smem_u32(const void* p) {
    unsigned a;
    asm("{ .reg .u64 t; cvta.to.shared.u64 t, %1; cvt.u32.u64 %0, t; }"
        : "=r"(a) : "l"(p));
    return a;
}

// -------- weight prep: transpose + fp32->fp16, plus qkv bias concat --------
__global__ __launch_bounds__(256)
void prep_all(const float* __restrict__ Wq, const float* __restrict__ Wk,
              const float* __restrict__ Wv, const float* __restrict__ Wo,
              const float* __restrict__ W1, const float* __restrict__ W2,
              const float* __restrict__ bq, const float* __restrict__ bk,
              const float* __restrict__ bv,
              __half* __restrict__ wqkv, __half* __restrict__ wot,
              __half* __restrict__ w1t, __half* __restrict__ w2t,
              float* __restrict__ bqkv)
{
    int bid = blockIdx.x;
    int tidf = threadIdx.y * 32 + threadIdx.x;
    if (bid >= 12288) {
        int i = (bid - 12288) * 256 + tidf;
        if (i < 3072)
            bqkv[i] = (i < 1024) ? bq[i] : (i < 2048 ? bk[i - 1024] : bv[i - 2048]);
        return;
    }
    const float* src; __half* dst; int K, N, base;
    if      (bid <  1024) { src = Wq; dst = wqkv;                   K = 1024; N = 1024; base = bid; }
    else if (bid <  2048) { src = Wk; dst = wqkv + 1024 * 1024;     K = 1024; N = 1024; base = bid - 1024; }
    else if (bid <  3072) { src = Wv; dst = wqkv + 2 * 1024 * 1024; K = 1024; N = 1024; base = bid - 2048; }
    else if (bid <  4096) { src = Wo; dst = wot;                    K = 1024; N = 1024; base = bid - 3072; }
    else if (bid <  8192) { src = W1; dst = w1t;                    K = 1024; N = 4096; base = bid - 4096; }
    else                  { src = W2; dst = w2t;                    K = 4096; N = 1024; base = bid - 8192; }
    int nb = N >> 5;
    int n0 = (base % nb) * 32, k0 = (base / nb) * 32;
    __shared__ float t[32][33];
    int x = threadIdx.x, y = threadIdx.y;
    #pragma unroll
    for (int i = 0; i < 32; i += 8)
        t[y + i][x] = src[(size_t)(k0 + y + i) * N + n0 + x];
    __syncthreads();
    #pragma unroll
    for (int i = 0; i < 32; i += 8)
        dst[(size_t)(n0 + y + i) * K + k0 + x] = __float2half_rn(t[x][y + i]);
}

// ---------------- LayerNorm: one warp per 1024-elem row --------------------
__global__ __launch_bounds__(256)
void ln_kernel(const float* __restrict__ x, const float* __restrict__ g,
               const float* __restrict__ b, __half* __restrict__ out)
{
    int w = threadIdx.x >> 5, lane = threadIdx.x & 31;
    int row = blockIdx.x * 8 + w;
    const float4* xr = (const float4*)(x + (size_t)row * EMB);

    float4 v[8];
    float s = 0.f, ss = 0.f;
    #pragma unroll
    for (int k = 0; k < 8; k++) {
        v[k] = xr[lane + k * 32];
        s  += v[k].x + v[k].y + v[k].z + v[k].w;
        ss += v[k].x*v[k].x + v[k].y*v[k].y + v[k].z*v[k].z + v[k].w*v[k].w;
    }
    #pragma unroll
    for (int o = 16; o; o >>= 1) {
        s  += __shfl_xor_sync(0xffffffffu, s,  o);
        ss += __shfl_xor_sync(0xffffffffu, ss, o);
    }
    float mu   = s * (1.f / EMB);
    float var  = ss * (1.f / EMB) - mu * mu;
    float rstd = rsqrtf(var + 1e-5f);

    uint2* orow = (uint2*)(out + (size_t)row * EMB);
    #pragma unroll
    for (int k = 0; k < 8; k++) {
        float4 gg = ((const float4*)g)[lane + k * 32];
        float4 bb = ((const float4*)b)[lane + k * 32];
        __half2 h0 = __floats2half2_rn((v[k].x - mu) * rstd * gg.x + bb.x,
                                       (v[k].y - mu) * rstd * gg.y + bb.y);
        __half2 h1 = __floats2half2_rn((v[k].z - mu) * rstd * gg.z + bb.z,
                                       (v[k].w - mu) * rstd * gg.w + bb.w);
        orow[lane + k * 32] = make_uint2(*(unsigned*)&h0, *(unsigned*)&h1);
    }
}

// ==================== fp16 mma.sync GEMM (k-slab 64, cp.async.cg) ==========
#define STG_B 36864                    // (128+128) rows * 144 B
#define TGEMM_SMEM (3 * STG_B)

template <int EPI, typename OutT>
__global__ __launch_bounds__(256)
void tgemm(const __half* __restrict__ A, const __half* __restrict__ Bt,
           const float* __restrict__ bias, const float* __restrict__ R,
           OutT* __restrict__ C, int N, int K)
{
    extern __shared__ char smem[];
    unsigned sbase = smem_u32(smem);
    int tid = threadIdx.x;
    int bx = blockIdx.x, by = blockIdx.y;

    size_t rowb = (size_t)K * 2;
    const char* Ag = (const char*)(A  + (size_t)(by * 128) * K);
    const char* Bg = (const char*)(Bt + (size_t)(bx * 128) * K);

    auto issue_tile = [&](int kt, int s) {
        unsigned stA = sbase + s * STG_B;
        unsigned stB = stA + 18432;
        size_t kofs = (size_t)kt * 128;
        #pragma unroll
        for (int i = 0; i < 4; i++) {
            int c = tid + i * 256;
            int row = c >> 3, q = c & 7;
            asm volatile("cp.async.cg.shared.global [%0], [%1], 16;"
                         :: "r"(stA + row * 144 + q * 16),
                            "l"(Ag + (size_t)row * rowb + kofs + q * 16));
        }
        #pragma unroll
        for (int i = 0; i < 4; i++) {
            int c = tid + i * 256;
            int row = c >> 3, q = c & 7;
            asm volatile("cp.async.cg.shared.global [%0], [%1], 16;"
                         :: "r"(stB + row * 144 + q * 16),
                            "l"(Bg + (size_t)row * rowb + kofs + q * 16));
        }
    };

    int T = K >> 6;
    issue_tile(0, 0); asm volatile("cp.async.commit_group;");
    issue_tile(1, 1); asm volatile("cp.async.commit_group;");

    int wid = tid >> 5, lane = tid & 31;
    int wm = wid >> 2, wn = wid & 3;
    int g = lane >> 2, t = lane & 3;
    int lrow = (lane & 7) + ((lane >> 3) & 1) * 8;
    int lk   = (lane >> 4) * 16;

    unsigned aoffb = (wm * 64 + lrow) * 144 + lk;
    unsigned boffb = (wn * 32 + lrow) * 144 + lk;

    float acc[4][4][4];
    #pragma unroll
    for (int mi = 0; mi < 4; mi++)
        #pragma unroll
        for (int ni = 0; ni < 4; ni++)
            #pragma unroll
            for (int r = 0; r < 4; r++) acc[mi][ni][r] = 0.f;

    for (int kt = 0; kt < T; kt++) {
        asm volatile("cp.async.wait_group 1;");
        __syncthreads();
        if (kt + 2 < T) issue_tile(kt + 2, (kt + 2) % 3);
        asm volatile("cp.async.commit_group;");

        int s = kt % 3;
        unsigned sA = sbase + s * STG_B;
        unsigned sB = sA + 18432;
        #pragma unroll
        for (int kk = 0; kk < 4; kk++) {
            unsigned a[4][4], bf[4][2];
            #pragma unroll
            for (int mi = 0; mi < 4; mi++)
                ldsm4(a[mi][0], a[mi][1], a[mi][2], a[mi][3],
                      sA + aoffb + mi * 16 * 144 + kk * 32);
            #pragma unroll
            for (int p = 0; p < 2; p++) {
                unsigned r0, r1, r2, r3;
                ldsm4(r0, r1, r2, r3, sB + boffb + p * 16 * 144 + kk * 32);
                bf[2*p][0] = r0; bf[2*p][1] = r2;
                bf[2*p+1][0] = r1; bf[2*p+1][1] = r3;
            }
            #pragma unroll
            for (int mi = 0; mi < 4; mi++)
                #pragma unroll
                for (int ni = 0; ni < 4; ni++)
                    mma_f16(acc[mi][ni], a[mi], bf[ni]);
        }
    }

    #pragma unroll
    for (int mi = 0; mi < 4; mi++) {
        int row = by * 128 + wm * 64 + mi * 16 + g;
        #pragma unroll
        for (int ni = 0; ni < 4; ni++) {
            int col = bx * 128 + wn * 32 + ni * 8 + t * 2;
            float b0 = bias[col], b1 = bias[col + 1];
            float v0 = acc[mi][ni][0] + b0;
            float v1 = acc[mi][ni][1] + b1;
            float v2 = acc[mi][ni][2] + b0;
            float v3 = acc[mi][ni][3] + b1;
            if (EPI == 1) {
                v0 = 0.5f * v0 * (1.f + erff(v0 * 0.70710678118654752f));
                v1 = 0.5f * v1 * (1.f + erff(v1 * 0.70710678118654752f));
                v2 = 0.5f * v2 * (1.f + erff(v2 * 0.70710678118654752f));
                v3 = 0.5f * v3 * (1.f + erff(v3 * 0.70710678118654752f));
            }
            if (EPI == 2) {
                v0 += R[(size_t)row * N + col];
                v1 += R[(size_t)row * N + col + 1];
                v2 += R[(size_t)(row + 8) * N + col];
                v3 += R[(size_t)(row + 8) * N + col + 1];
            }
            if constexpr (sizeof(OutT) == 2) {
                *(__half2*)((__half*)C + (size_t)row * N + col)       = __floats2half2_rn(v0, v1);
                *(__half2*)((__half*)C + (size_t)(row + 8) * N + col) = __floats2half2_rn(v2, v3);
            } else {
                *(float2*)((float*)C + (size_t)row * N + col)       = make_float2(v0, v1);
                *(float2*)((float*)C + (size_t)(row + 8) * N + col) = make_float2(v2, v3);
            }
        }
    }
}

// ------- fp16 flash attention: register-P, 4 CTAs/SM forced ----------------
// smem (bytes): Ks 2x9216 | Vs 2x9216 | Qs 9216   (stride 72 halves = 144 B)
#define ATT_SMEM 46080
__global__ __launch_bounds__(128, 4)
void attn_kernel(const __half* __restrict__ qkv, __half* __restrict__ y)
{
    extern __shared__ __half smh[];
    unsigned uS = smem_u32(smh);
    unsigned uV = uS + 18432;
    unsigned uQ = uS + 36864;

    int qt = (int)gridDim.x - 1 - (int)blockIdx.x;
    int h = blockIdx.y, b = blockIdx.z;
    int tid = threadIdx.x, wq = tid >> 5, lane = tid & 31;
    int g = lane >> 2, t = lane & 3;
    int lrow = (lane & 7) + ((lane >> 3) & 1) * 8;
    int lk   = (lane >> 4) * 16;

    const __half* qkvb = qkv + (size_t)(b * SEQ) * 3072 + h * HD;
    int crow = tid >> 3, cq16 = (tid & 7) * 16;

    auto issue_tile = [&](int kt, int s) {
        #pragma unroll
        for (int i = 0; i < 4; i++) {
            int row = crow + i * 16;
            const char* src = (const char*)(qkvb + (size_t)(kt * 64 + row) * 3072);
            unsigned dofs = s * 9216 + row * 144 + cq16;
            asm volatile("cp.async.ca.shared.global [%0], [%1], 16;"
                         :: "r"(uS + dofs), "l"(src + 2048 + cq16));
            asm volatile("cp.async.ca.shared.global [%0], [%1], 16;"
                         :: "r"(uV + dofs), "l"(src + 4096 + cq16));
        }
    };
    issue_tile(0, 0);
    asm volatile("cp.async.commit_group;");

    // stage Q
    for (int c = tid; c < 512; c += 128) {
        int row = c >> 3, qo = (c & 7) * 8;
        *(uint4*)&smh[18432 + row * 72 + qo] =
            *(const uint4*)(qkvb + (size_t)(qt * 64 + row) * 3072 + qo);
    }
    __syncthreads();

    unsigned aoffb = (wq * 16 + lrow) * 144 + lk;
    unsigned qa[4][4];
    #pragma unroll
    for (int kb = 0; kb < 4; kb++)
        ldsm4(qa[kb][0], qa[kb][1], qa[kb][2], qa[kb][3], uQ + aoffb + kb * 32);
    // pre-scale Q fragments by 1/8 (exact in fp16)
    {
        __half2 s8 = __float2half2_rn(0.125f);
        #pragma unroll
        for (int kb = 0; kb < 4; kb++)
            #pragma unroll
            for (int i = 0; i < 4; i++) {
                __half2 hv = __hmul2(*(__half2*)&qa[kb][i], s8);
                qa[kb][i] = *(unsigned*)&hv;
            }
    }

    unsigned boffb = lrow * 144 + lk;

    float oacc[8][4];
    #pragma unroll
    for (int nb = 0; nb < 8; nb++)
        #pragma unroll
        for (int r = 0; r < 4; r++) oacc[nb][r] = 0.f;
    float mr[2] = {-1e30f, -1e30f}, ls[2] = {0.f, 0.f};

    for (int kt = 0; kt <= qt; kt++) {
        int s = kt & 1;
        asm volatile("cp.async.wait_group 0;");
        __syncthreads();
        if (kt < qt) {
            issue_tile(kt + 1, s ^ 1);
            asm volatile("cp.async.commit_group;");
        }
        unsigned sK = uS + s * 9216;
        unsigned sV = uV + s * 9216;

        // S = Q K^T (Q pre-scaled)
        float sc[8][4];
        #pragma unroll
        for (int nb = 0; nb < 8; nb++)
            #pragma unroll
            for (int r = 0; r < 4; r++) sc[nb][r] = 0.f;
        #pragma unroll
        for (int kb = 0; kb < 4; kb++) {
            unsigned bk[8][2];
            #pragma unroll
            for (int p = 0; p < 4; p++) {
                unsigned r0, r1, r2, r3;
                ldsm4(r0, r1, r2, r3, sK + boffb + p * 16 * 144 + kb * 32);
                bk[2*p][0] = r0; bk[2*p][1] = r2;
                bk[2*p+1][0] = r1; bk[2*p+1][1] = r3;
            }
            #pragma unroll
            for (int nb = 0; nb < 8; nb++)
                mma_f16(sc[nb], qa[kb], bk[nb]);
        }

        if (kt == qt) {
            int row0 = wq * 16 + g;
            #pragma unroll
            for (int nb = 0; nb < 8; nb++) {
                int col = nb * 8 + 2 * t;
                if (col     > row0)     sc[nb][0] = -1e30f;
                if (col + 1 > row0)     sc[nb][1] = -1e30f;
                if (col     > row0 + 8) sc[nb][2] = -1e30f;
                if (col + 1 > row0 + 8) sc[nb][3] = -1e30f;
            }
        }

        float rm0 = -1e30f, rm1 = -1e30f;
        #pragma unroll
        for (int nb = 0; nb < 8; nb++) {
            rm0 = fmaxf(rm0, fmaxf(sc[nb][0], sc[nb][1]));
            rm1 = fmaxf(rm1, fmaxf(sc[nb][2], sc[nb][3]));
        }
        rm0 = fmaxf(rm0, __shfl_xor_sync(0xffffffffu, rm0, 1));
        rm0 = fmaxf(rm0, __shfl_xor_sync(0xffffffffu, rm0, 2));
        rm1 = fmaxf(rm1, __shfl_xor_sync(0xffffffffu, rm1, 1));
        rm1 = fmaxf(rm1, __shfl_xor_sync(0xffffffffu, rm1, 2));
        float mn0 = fmaxf(mr[0], rm0), mn1 = fmaxf(mr[1], rm1);
        float co0 = fexp(mr[0] - mn0), co1 = fexp(mr[1] - mn1);
        mr[0] = mn0; mr[1] = mn1;

        // exp + convert P to A-fragment registers (no smem round trip)
        unsigned ph[8][2];
        float su0 = 0.f, su1 = 0.f;
        #pragma unroll
        for (int nb = 0; nb < 8; nb++) {
            float p0 = fexp(sc[nb][0] - mn0);
            float p1 = fexp(sc[nb][1] - mn0);
            float p2 = fexp(sc[nb][2] - mn1);
            float p3 = fexp(sc[nb][3] - mn1);
            su0 += p0 + p1; su1 += p2 + p3;
            __half2 h01 = __floats2half2_rn(p0, p1);
            __half2 h23 = __floats2half2_rn(p2, p3);
            ph[nb][0] = *(unsigned*)&h01;
            ph[nb][1] = *(unsigned*)&h23;
        }
        su0 += __shfl_xor_sync(0xffffffffu, su0, 1);
        su0 += __shfl_xor_sync(0xffffffffu, su0, 2);
        su1 += __shfl_xor_sync(0xffffffffu, su1, 1);
        su1 += __shfl_xor_sync(0xffffffffu, su1, 2);
        ls[0] = ls[0] * co0 + su0;
        ls[1] = ls[1] * co1 + su1;
        #pragma unroll
        for (int nb = 0; nb < 8; nb++) {
            oacc[nb][0] *= co0; oacc[nb][1] *= co0;
            oacc[nb][2] *= co1; oacc[nb][3] *= co1;
        }

        // O += P V  (P straight from registers; V via ldsm.trans)
        #pragma unroll
        for (int kb = 0; kb < 4; kb++) {
            unsigned pa[4] = {ph[2*kb][0], ph[2*kb][1], ph[2*kb+1][0], ph[2*kb+1][1]};
            unsigned vb[8][2];
            #pragma unroll
            for (int p = 0; p < 4; p++) {
                unsigned r0, r1, r2, r3;
                ldsm4t(r0, r1, r2, r3, sV + (kb * 16 + lrow) * 144 + p * 32 + lk);
                vb[2*p][0] = r0; vb[2*p][1] = r1;
                vb[2*p+1][0] = r2; vb[2*p+1][1] = r3;
            }
            #pragma unroll
            for (int nb = 0; nb < 8; nb++)
                mma_f16(oacc[nb], pa, vb[nb]);
        }
    }

    float inv0 = 1.f / ls[0], inv1 = 1.f / ls[1];
    int row0 = qt * 64 + wq * 16 + g;
    #pragma unroll
    for (int nb = 0; nb < 8; nb++) {
        int col = nb * 8 + 2 * t;
        *(__half2*)(y + (size_t)(b * SEQ + row0) * EMB + h * HD + col) =
            __floats2half2_rn(oacc[nb][0] * inv0, oacc[nb][1] * inv0);
        *(__half2*)(y + (size_t)(b * SEQ + row0 + 8) * EMB + h * HD + col) =
            __floats2half2_rn(oacc[nb][2] * inv1, oacc[nb][3] * inv1);
    }
}

// ---------------- launcher -------------------------------------------------
extern "C" void kernel_launch(void* const* d_in, const int* in_sizes, int n_in,
                              void* d_out, int out_size)
{
    const float* x     = (const float*)d_in[0];
    const float* Wq    = (const float*)d_in[1];
    const float* bq    = (const float*)d_in[2];
    const float* Wk    = (const float*)d_in[3];
    const float* bk    = (const float*)d_in[4];
    const float* Wv    = (const float*)d_in[5];
    const float* bv    = (const float*)d_in[6];
    const float* Wo    = (const float*)d_in[7];
    const float* bo    = (const float*)d_in[8];
    const float* g1    = (const float*)d_in[9];
    const float* beta1 = (const float*)d_in[10];
    const float* g2    = (const float*)d_in[11];
    const float* beta2 = (const float*)d_in[12];
    const float* W1    = (const float*)d_in[13];
    const float* b1f   = (const float*)d_in[14];
    const float* W2    = (const float*)d_in[15];
    const float* b2    = (const float*)d_in[16];
    float* out = (float*)d_out;

    __half *h, *qkv, *yb, *ff, *wqkv, *wot, *w1t, *w2t;
    float *x2, *bqkv;
    cudaGetSymbolAddress((void**)&h,    g_h);
    cudaGetSymbolAddress((void**)&qkv,  g_qkv);
    cudaGetSymbolAddress((void**)&yb,   g_y);
    cudaGetSymbolAddress((void**)&x2,   g_x2);
    cudaGetSymbolAddress((void**)&ff,   g_ff);
    cudaGetSymbolAddress((void**)&wqkv, g_wqkv);
    cudaGetSymbolAddress((void**)&wot,  g_wot);
    cudaGetSymbolAddress((void**)&w1t,  g_w1t);
    cudaGetSymbolAddress((void**)&w2t,  g_w2t);
    cudaGetSymbolAddress((void**)&bqkv, g_bqkv);

    cudaFuncSetAttribute(tgemm<0, __half>, cudaFuncAttributeMaxDynamicSharedMemorySize, TGEMM_SMEM);
    cudaFuncSetAttribute(tgemm<1, __half>, cudaFuncAttributeMaxDynamicSharedMemorySize, TGEMM_SMEM);
    cudaFuncSetAttribute(tgemm<2, float>,  cudaFuncAttributeMaxDynamicSharedMemorySize, TGEMM_SMEM);
    cudaFuncSetAttribute(attn_kernel, cudaFuncAttributeMaxDynamicSharedMemorySize, ATT_SMEM);

    prep_all<<<12300, dim3(32, 8)>>>(Wq, Wk, Wv, Wo, W1, W2, bq, bk, bv,
                                     wqkv, wot, w1t, w2t, bqkv);

    ln_kernel<<<N_TOK / 8, 256>>>(x, g1, beta1, h);
    tgemm<0, __half><<<dim3(24, 64), 256, TGEMM_SMEM>>>(h, wqkv, bqkv, nullptr, qkv, 3 * EMB, EMB);
    attn_kernel<<<dim3(SEQ / 64, NH, NB), 128, ATT_SMEM>>>(qkv, yb);
    tgemm<2, float><<<dim3(8, 64), 256, TGEMM_SMEM>>>(yb, wot, bo, x, x2, EMB, EMB);
    ln_kernel<<<N_TOK / 8, 256>>>(x2, g2, beta2, h);
    tgemm<1, __half><<<dim3(32, 64), 256, TGEMM_SMEM>>>(h, w1t, b1f, nullptr, ff, FFD, EMB);
    tgemm<2, float><<<dim3(8, 64), 256, TGEMM_SMEM>>>(ff, w2t, b2, x2, out, EMB, FFD);
}

// round 17
// speedup vs baseline: 1.0318x; 1.0318x over previous
#include <cuda_runtime.h>
#include <cuda_fp16.h>

#define N_TOK 8192
#define EMB   1024
#define FFD   4096
#define SEQ   2048
#define NB    4
#define NH    16
#define HD    64

// ---------------- scratch ----------------
__device__ __half g_h  [N_TOK * EMB];
__device__ __half g_qkv[(size_t)N_TOK * 3 * EMB];
__device__ __half g_y  [N_TOK * EMB];
__device__ float  g_x2 [N_TOK * EMB];
__device__ __half g_ff [(size_t)N_TOK * FFD];
__device__ __half g_wqkv[3 * EMB * EMB];
__device__ __half g_wot [EMB * EMB];
__device__ __half g_w1t [(size_t)FFD * EMB];
__device__ __half g_w2t [(size_t)EMB * FFD];
__device__ float  g_bqkv[3 * EMB];

// fast exp on the FMA pipe
__device__ __forceinline__ float fexp(float x) {
    float t = fmaxf(x * 1.4426950408889634f, -126.0f);
    float fm = t + 12582912.0f;
    int   ib = __float_as_int(fm);
    float f  = t - (fm - 12582912.0f);
    float p = 1.33335581464284e-3f;
    p = fmaf(p, f, 9.61812910762848e-3f);
    p = fmaf(p, f, 5.55041086648216e-2f);
    p = fmaf(p, f, 2.40226506959101e-1f);
    p = fmaf(p, f, 6.93147180559945e-1f);
    p = fmaf(p, f, 1.0f);
    unsigned sc = ((unsigned)ib << 23) + 0x3f800000u;
    return p * __uint_as_float(sc);
}

__device__ __forceinline__ void ldsm4(unsigned& r0, unsigned& r1, unsigned& r2,
                                      unsigned& r3, unsigned addr) {
    asm volatile("ldmatrix.sync.aligned.m8n8.x4.shared.b16 {%0,%1,%2,%3}, [%4];\n"
                 : "=r"(r0), "=r"(r1), "=r"(r2), "=r"(r3) : "r"(addr));
}

__device__ __forceinline__ void ldsm4t(unsigned& r0, unsigned& r1, unsigned& r2,
                                       unsigned& r3, unsigned addr) {
    asm volatile("ldmatrix.sync.aligned.m8n8.x4.trans.shared.b16 {%0,%1,%2,%3}, [%4];\n"
                 : "=r"(r0), "=r"(r1), "=r"(r2), "=r"(r3) : "r"(addr));
}

__device__ __forceinline__ void mma_f16(float* d, const unsigned* a, const unsigned* b) {
    asm volatile(
        "mma.sync.aligned.m16n8k16.row.col.f32.f16.f16.f32 "
        "{%0,%1,%2,%3}, {%4,%5,%6,%7}, {%8,%9}, {%0,%1,%2,%3};\n"
        : "+f"(d[0]), "+f"(d[1]), "+f"(d[2]), "+f"(d[3])
        : "r"(a[0]), "r"(a[1]), "r"(a[2]), "r"(a[3]), "r"(b[0]), "r"(b[1]));
}

__device__ __forceinline__ unsigned smem_u32(const void* p) {
    unsigned a;
    asm("{ .reg .u64 t; cvta.to.shared.u64 t, %1; cvt.u32.u64 %0, t; }"
        : "=r"(a) : "l"(p));
    return a;
}

// -------- weight prep: transpose + fp32->fp16, plus qkv bias concat --------
__global__ __launch_bounds__(256)
void prep_all(const float* __restrict__ Wq, const float* __restrict__ Wk,
              const float* __restrict__ Wv, const float* __restrict__ Wo,
              const float* __restrict__ W1, const float* __restrict__ W2,
              const float* __restrict__ bq, const float* __restrict__ bk,
              const float* __restrict__ bv,
              __half* __restrict__ wqkv, __half* __restrict__ wot,
              __half* __restrict__ w1t, __half* __restrict__ w2t,
              float* __restrict__ bqkv)
{
    int bid = blockIdx.x;
    int tidf = threadIdx.y * 32 + threadIdx.x;
    if (bid >= 12288) {
        int i = (bid - 12288) * 256 + tidf;
        if (i < 3072)
            bqkv[i] = (i < 1024) ? bq[i] : (i < 2048 ? bk[i - 1024] : bv[i - 2048]);
        return;
    }
    const float* src; __half* dst; int K, N, base;
    if      (bid <  1024) { src = Wq; dst = wqkv;                   K = 1024; N = 1024; base = bid; }
    else if (bid <  2048) { src = Wk; dst = wqkv + 1024 * 1024;     K = 1024; N = 1024; base = bid - 1024; }
    else if (bid <  3072) { src = Wv; dst = wqkv + 2 * 1024 * 1024; K = 1024; N = 1024; base = bid - 2048; }
    else if (bid <  4096) { src = Wo; dst = wot;                    K = 1024; N = 1024; base = bid - 3072; }
    else if (bid <  8192) { src = W1; dst = w1t;                    K = 1024; N = 4096; base = bid - 4096; }
    else                  { src = W2; dst = w2t;                    K = 4096; N = 1024; base = bid - 8192; }
    int nb = N >> 5;
    int n0 = (base % nb) * 32, k0 = (base / nb) * 32;
    __shared__ float t[32][33];
    int x = threadIdx.x, y = threadIdx.y;
    #pragma unroll
    for (int i = 0; i < 32; i += 8)
        t[y + i][x] = src[(size_t)(k0 + y + i) * N + n0 + x];
    __syncthreads();
    #pragma unroll
    for (int i = 0; i < 32; i += 8)
        dst[(size_t)(n0 + y + i) * K + k0 + x] = __float2half_rn(t[x][y + i]);
}

// ---------------- LayerNorm: one warp per 1024-elem row --------------------
__global__ __launch_bounds__(256)
void ln_kernel(const float* __restrict__ x, const float* __restrict__ g,
               const float* __restrict__ b, __half* __restrict__ out)
{
    int w = threadIdx.x >> 5, lane = threadIdx.x & 31;
    int row = blockIdx.x * 8 + w;
    const float4* xr = (const float4*)(x + (size_t)row * EMB);

    float4 v[8];
    float s = 0.f, ss = 0.f;
    #pragma unroll
    for (int k = 0; k < 8; k++) {
        v[k] = xr[lane + k * 32];
        s  += v[k].x + v[k].y + v[k].z + v[k].w;
        ss += v[k].x*v[k].x + v[k].y*v[k].y + v[k].z*v[k].z + v[k].w*v[k].w;
    }
    #pragma unroll
    for (int o = 16; o; o >>= 1) {
        s  += __shfl_xor_sync(0xffffffffu, s,  o);
        ss += __shfl_xor_sync(0xffffffffu, ss, o);
    }
    float mu   = s * (1.f / EMB);
    float var  = ss * (1.f / EMB) - mu * mu;
    float rstd = rsqrtf(var + 1e-5f);

    uint2* orow = (uint2*)(out + (size_t)row * EMB);
    #pragma unroll
    for (int k = 0; k < 8; k++) {
        float4 gg = ((const float4*)g)[lane + k * 32];
        float4 bb = ((const float4*)b)[lane + k * 32];
        __half2 h0 = __floats2half2_rn((v[k].x - mu) * rstd * gg.x + bb.x,
                                       (v[k].y - mu) * rstd * gg.y + bb.y);
        __half2 h1 = __floats2half2_rn((v[k].z - mu) * rstd * gg.z + bb.z,
                                       (v[k].w - mu) * rstd * gg.w + bb.w);
        orow[lane + k * 32] = make_uint2(*(unsigned*)&h0, *(unsigned*)&h1);
    }
}

// ==================== fp16 mma.sync GEMM (k-slab 64, cp.async.ca) ==========
#define STG_B 36864                    // (128+128) rows * 144 B
#define TGEMM_SMEM (3 * STG_B)

template <int EPI, typename OutT>
__global__ __launch_bounds__(256)
void tgemm(const __half* __restrict__ A, const __half* __restrict__ Bt,
           const float* __restrict__ bias, const float* __restrict__ R,
           OutT* __restrict__ C, int N, int K)
{
    extern __shared__ char smem[];
    unsigned sbase = smem_u32(smem);
    int tid = threadIdx.x;
    int bx = blockIdx.x, by = blockIdx.y;

    size_t rowb = (size_t)K * 2;
    const char* Ag = (const char*)(A  + (size_t)(by * 128) * K);
    const char* Bg = (const char*)(Bt + (size_t)(bx * 128) * K);

    auto issue_tile = [&](int kt, int s) {
        unsigned stA = sbase + s * STG_B;
        unsigned stB = stA + 18432;
        size_t kofs = (size_t)kt * 128;
        #pragma unroll
        for (int i = 0; i < 4; i++) {
            int c = tid + i * 256;
            int row = c >> 3, q = c & 7;
            asm volatile("cp.async.ca.shared.global [%0], [%1], 16;"
                         :: "r"(stA + row * 144 + q * 16),
                            "l"(Ag + (size_t)row * rowb + kofs + q * 16));
        }
        #pragma unroll
        for (int i = 0; i < 4; i++) {
            int c = tid + i * 256;
            int row = c >> 3, q = c & 7;
            asm volatile("cp.async.ca.shared.global [%0], [%1], 16;"
                         :: "r"(stB + row * 144 + q * 16),
                            "l"(Bg + (size_t)row * rowb + kofs + q * 16));
        }
    };

    int T = K >> 6;
    issue_tile(0, 0); asm volatile("cp.async.commit_group;");
    issue_tile(1, 1); asm volatile("cp.async.commit_group;");

    int wid = tid >> 5, lane = tid & 31;
    int wm = wid >> 2, wn = wid & 3;
    int g = lane >> 2, t = lane & 3;
    int lrow = (lane & 7) + ((lane >> 3) & 1) * 8;
    int lk   = (lane >> 4) * 16;

    unsigned aoffb = (wm * 64 + lrow) * 144 + lk;
    unsigned boffb = (wn * 32 + lrow) * 144 + lk;

    float acc[4][4][4];
    #pragma unroll
    for (int mi = 0; mi < 4; mi++)
        #pragma unroll
        for (int ni = 0; ni < 4; ni++)
            #pragma unroll
            for (int r = 0; r < 4; r++) acc[mi][ni][r] = 0.f;

    for (int kt = 0; kt < T; kt++) {
        asm volatile("cp.async.wait_group 1;");
        __syncthreads();
        if (kt + 2 < T) issue_tile(kt + 2, (kt + 2) % 3);
        asm volatile("cp.async.commit_group;");

        int s = kt % 3;
        unsigned sA = sbase + s * STG_B;
        unsigned sB = sA + 18432;
        #pragma unroll
        for (int kk = 0; kk < 4; kk++) {
            unsigned a[4][4], bf[4][2];
            #pragma unroll
            for (int mi = 0; mi < 4; mi++)
                ldsm4(a[mi][0], a[mi][1], a[mi][2], a[mi][3],
                      sA + aoffb + mi * 16 * 144 + kk * 32);
            #pragma unroll
            for (int p = 0; p < 2; p++) {
                unsigned r0, r1, r2, r3;
                ldsm4(r0, r1, r2, r3, sB + boffb + p * 16 * 144 + kk * 32);
                bf[2*p][0] = r0; bf[2*p][1] = r2;
                bf[2*p+1][0] = r1; bf[2*p+1][1] = r3;
            }
            #pragma unroll
            for (int mi = 0; mi < 4; mi++)
                #pragma unroll
                for (int ni = 0; ni < 4; ni++)
                    mma_f16(acc[mi][ni], a[mi], bf[ni]);
        }
    }

    #pragma unroll
    for (int mi = 0; mi < 4; mi++) {
        int row = by * 128 + wm * 64 + mi * 16 + g;
        #pragma unroll
        for (int ni = 0; ni < 4; ni++) {
            int col = bx * 128 + wn * 32 + ni * 8 + t * 2;
            float b0 = bias[col], b1 = bias[col + 1];
            float v0 = acc[mi][ni][0] + b0;
            float v1 = acc[mi][ni][1] + b1;
            float v2 = acc[mi][ni][2] + b0;
            float v3 = acc[mi][ni][3] + b1;
            if (EPI == 1) {
                v0 = 0.5f * v0 * (1.f + erff(v0 * 0.70710678118654752f));
                v1 = 0.5f * v1 * (1.f + erff(v1 * 0.70710678118654752f));
                v2 = 0.5f * v2 * (1.f + erff(v2 * 0.70710678118654752f));
                v3 = 0.5f * v3 * (1.f + erff(v3 * 0.70710678118654752f));
            }
            if (EPI == 2) {
                v0 += R[(size_t)row * N + col];
                v1 += R[(size_t)row * N + col + 1];
                v2 += R[(size_t)(row + 8) * N + col];
                v3 += R[(size_t)(row + 8) * N + col + 1];
            }
            if constexpr (sizeof(OutT) == 2) {
                *(__half2*)((__half*)C + (size_t)row * N + col)       = __floats2half2_rn(v0, v1);
                *(__half2*)((__half*)C + (size_t)(row + 8) * N + col) = __floats2half2_rn(v2, v3);
            } else {
                *(float2*)((float*)C + (size_t)row * N + col)       = make_float2(v0, v1);
                *(float2*)((float*)C + (size_t)(row + 8) * N + col) = make_float2(v2, v3);
            }
        }
    }
}

// ------- fp16 flash attention: register-P, 4 CTAs/SM forced ----------------
// smem (bytes): Ks 2x9216 | Vs 2x9216 | Qs 9216   (stride 72 halves = 144 B)
#define ATT_SMEM 46080
__global__ __launch_bounds__(128, 4)
void attn_kernel(const __half* __restrict__ qkv, __half* __restrict__ y)
{
    extern __shared__ __half smh[];
    unsigned uS = smem_u32(smh);
    unsigned uV = uS + 18432;
    unsigned uQ = uS + 36864;

    int qt = (int)gridDim.x - 1 - (int)blockIdx.x;
    int h = blockIdx.y, b = blockIdx.z;
    int tid = threadIdx.x, wq = tid >> 5, lane = tid & 31;
    int g = lane >> 2, t = lane & 3;
    int lrow = (lane & 7) + ((lane >> 3) & 1) * 8;
    int lk   = (lane >> 4) * 16;

    const __half* qkvb = qkv + (size_t)(b * SEQ) * 3072 + h * HD;
    int crow = tid >> 3, cq16 = (tid & 7) * 16;

    auto issue_tile = [&](int kt, int s) {
        #pragma unroll
        for (int i = 0; i < 4; i++) {
            int row = crow + i * 16;
            const char* src = (const char*)(qkvb + (size_t)(kt * 64 + row) * 3072);
            unsigned dofs = s * 9216 + row * 144 + cq16;
            asm volatile("cp.async.ca.shared.global [%0], [%1], 16;"
                         :: "r"(uS + dofs), "l"(src + 2048 + cq16));
            asm volatile("cp.async.ca.shared.global [%0], [%1], 16;"
                         :: "r"(uV + dofs), "l"(src + 4096 + cq16));
        }
    };
    issue_tile(0, 0);
    asm volatile("cp.async.commit_group;");

    // stage Q
    for (int c = tid; c < 512; c += 128) {
        int row = c >> 3, qo = (c & 7) * 8;
        *(uint4*)&smh[18432 + row * 72 + qo] =
            *(const uint4*)(qkvb + (size_t)(qt * 64 + row) * 3072 + qo);
    }
    __syncthreads();

    unsigned aoffb = (wq * 16 + lrow) * 144 + lk;
    unsigned qa[4][4];
    #pragma unroll
    for (int kb = 0; kb < 4; kb++)
        ldsm4(qa[kb][0], qa[kb][1], qa[kb][2], qa[kb][3], uQ + aoffb + kb * 32);
    // pre-scale Q fragments by 1/8 (exact in fp16)
    {
        __half2 s8 = __float2half2_rn(0.125f);
        #pragma unroll
        for (int kb = 0; kb < 4; kb++)
            #pragma unroll
            for (int i = 0; i < 4; i++) {
                __half2 hv = __hmul2(*(__half2*)&qa[kb][i], s8);
                qa[kb][i] = *(unsigned*)&hv;
            }
    }

    unsigned boffb = lrow * 144 + lk;

    float oacc[8][4];
    #pragma unroll
    for (int nb = 0; nb < 8; nb++)
        #pragma unroll
        for (int r = 0; r < 4; r++) oacc[nb][r] = 0.f;
    float mr[2] = {-1e30f, -1e30f}, ls[2] = {0.f, 0.f};

    for (int kt = 0; kt <= qt; kt++) {
        int s = kt & 1;
        asm volatile("cp.async.wait_group 0;");
        __syncthreads();
        if (kt < qt) {
            issue_tile(kt + 1, s ^ 1);
            asm volatile("cp.async.commit_group;");
        }
        unsigned sK = uS + s * 9216;
        unsigned sV = uV + s * 9216;

        // S = Q K^T (Q pre-scaled)
        float sc[8][4];
        #pragma unroll
        for (int nb = 0; nb < 8; nb++)
            #pragma unroll
            for (int r = 0; r < 4; r++) sc[nb][r] = 0.f;
        #pragma unroll
        for (int kb = 0; kb < 4; kb++) {
            unsigned bk[8][2];
            #pragma unroll
            for (int p = 0; p < 4; p++) {
                unsigned r0, r1, r2, r3;
                ldsm4(r0, r1, r2, r3, sK + boffb + p * 16 * 144 + kb * 32);
                bk[2*p][0] = r0; bk[2*p][1] = r2;
                bk[2*p+1][0] = r1; bk[2*p+1][1] = r3;
            }
            #pragma unroll
            for (int nb = 0; nb < 8; nb++)
                mma_f16(sc[nb], qa[kb], bk[nb]);
        }

        if (kt == qt) {
            int row0 = wq * 16 + g;
            #pragma unroll
            for (int nb = 0; nb < 8; nb++) {
                int col = nb * 8 + 2 * t;
                if (col     > row0)     sc[nb][0] = -1e30f;
                if (col + 1 > row0)     sc[nb][1] = -1e30f;
                if (col     > row0 + 8) sc[nb][2] = -1e30f;
                if (col + 1 > row0 + 8) sc[nb][3] = -1e30f;
            }
        }

        float rm0 = -1e30f, rm1 = -1e30f;
        #pragma unroll
        for (int nb = 0; nb < 8; nb++) {
            rm0 = fmaxf(rm0, fmaxf(sc[nb][0], sc[nb][1]));
            rm1 = fmaxf(rm1, fmaxf(sc[nb][2], sc[nb][3]));
        }
        rm0 = fmaxf(rm0, __shfl_xor_sync(0xffffffffu, rm0, 1));
        rm0 = fmaxf(rm0, __shfl_xor_sync(0xffffffffu, rm0, 2));
        rm1 = fmaxf(rm1, __shfl_xor_sync(0xffffffffu, rm1, 1));
        rm1 = fmaxf(rm1, __shfl_xor_sync(0xffffffffu, rm1, 2));
        float mn0 = fmaxf(mr[0], rm0), mn1 = fmaxf(mr[1], rm1);
        float co0 = fexp(mr[0] - mn0), co1 = fexp(mr[1] - mn1);
        mr[0] = mn0; mr[1] = mn1;

        // exp + convert P to A-fragment registers (no smem round trip)
        unsigned ph[8][2];
        float su0 = 0.f, su1 = 0.f;
        #pragma unroll
        for (int nb = 0; nb < 8; nb++) {
            float p0 = fexp(sc[nb][0] - mn0);
            float p1 = fexp(sc[nb][1] - mn0);
            float p2 = fexp(sc[nb][2] - mn1);
            float p3 = fexp(sc[nb][3] - mn1);
            su0 += p0 + p1; su1 += p2 + p3;
            __half2 h01 = __floats2half2_rn(p0, p1);
            __half2 h23 = __floats2half2_rn(p2, p3);
            ph[nb][0] = *(unsigned*)&h01;
            ph[nb][1] = *(unsigned*)&h23;
        }
        su0 += __shfl_xor_sync(0xffffffffu, su0, 1);
        su0 += __shfl_xor_sync(0xffffffffu, su0, 2);
        su1 += __shfl_xor_sync(0xffffffffu, su1, 1);
        su1 += __shfl_xor_sync(0xffffffffu, su1, 2);
        ls[0] = ls[0] * co0 + su0;
        ls[1] = ls[1] * co1 + su1;
        #pragma unroll
        for (int nb = 0; nb < 8; nb++) {
            oacc[nb][0] *= co0; oacc[nb][1] *= co0;
            oacc[nb][2] *= co1; oacc[nb][3] *= co1;
        }

        // O += P V  (P straight from registers; V via ldsm.trans)
        #pragma unroll
        for (int kb = 0; kb < 4; kb++) {
            unsigned pa[4] = {ph[2*kb][0], ph[2*kb][1], ph[2*kb+1][0], ph[2*kb+1][1]};
            unsigned vb[8][2];
            #pragma unroll
            for (int p = 0; p < 4; p++) {
                unsigned r0, r1, r2, r3;
                ldsm4t(r0, r1, r2, r3, sV + (kb * 16 + lrow) * 144 + p * 32 + lk);
                vb[2*p][0] = r0; vb[2*p][1] = r1;
                vb[2*p+1][0] = r2; vb[2*p+1][1] = r3;
            }
            #pragma unroll
            for (int nb = 0; nb < 8; nb++)
                mma_f16(oacc[nb], pa, vb[nb]);
        }
    }

    float inv0 = 1.f / ls[0], inv1 = 1.f / ls[1];
    int row0 = qt * 64 + wq * 16 + g;
    #pragma unroll
    for (int nb = 0; nb < 8; nb++) {
        int col = nb * 8 + 2 * t;
        *(__half2*)(y + (size_t)(b * SEQ + row0) * EMB + h * HD + col) =
            __floats2half2_rn(oacc[nb][0] * inv0, oacc[nb][1] * inv0);
        *(__half2*)(y + (size_t)(b * SEQ + row0 + 8) * EMB + h * HD + col) =
            __floats2half2_rn(oacc[nb][2] * inv1, oacc[nb][3] * inv1);
    }
}

// ---------------- launcher -------------------------------------------------
extern "C" void kernel_launch(void* const* d_in, const int* in_sizes, int n_in,
                              void* d_out, int out_size)
{
    const float* x     = (const float*)d_in[0];
    const float* Wq    = (const float*)d_in[1];
    const float* bq    = (const float*)d_in[2];
    const float* Wk    = (const float*)d_in[3];
    const float* bk    = (const float*)d_in[4];
    const float* Wv    = (const float*)d_in[5];
    const float* bv    = (const float*)d_in[6];
    const float* Wo    = (const float*)d_in[7];
    const float* bo    = (const float*)d_in[8];
    const float* g1    = (const float*)d_in[9];
    const float* beta1 = (const float*)d_in[10];
    const float* g2    = (const float*)d_in[11];
    const float* beta2 = (const float*)d_in[12];
    const float* W1    = (const float*)d_in[13];
    const float* b1f   = (const float*)d_in[14];
    const float* W2    = (const float*)d_in[15];
    const float* b2    = (const float*)d_in[16];
    float* out = (float*)d_out;

    __half *h, *qkv, *yb, *ff, *wqkv, *wot, *w1t, *w2t;
    float *x2, *bqkv;
    cudaGetSymbolAddress((void**)&h,    g_h);
    cudaGetSymbolAddress((void**)&qkv,  g_qkv);
    cudaGetSymbolAddress((void**)&yb,   g_y);
    cudaGetSymbolAddress((void**)&x2,   g_x2);
    cudaGetSymbolAddress((void**)&ff,   g_ff);
    cudaGetSymbolAddress((void**)&wqkv, g_wqkv);
    cudaGetSymbolAddress((void**)&wot,  g_wot);
    cudaGetSymbolAddress((void**)&w1t,  g_w1t);
    cudaGetSymbolAddress((void**)&w2t,  g_w2t);
    cudaGetSymbolAddress((void**)&bqkv, g_bqkv);

    cudaFuncSetAttribute(tgemm<0, __half>, cudaFuncAttributeMaxDynamicSharedMemorySize, TGEMM_SMEM);
    cudaFuncSetAttribute(tgemm<1, __half>, cudaFuncAttributeMaxDynamicSharedMemorySize, TGEMM_SMEM);
    cudaFuncSetAttribute(tgemm<2, float>,  cudaFuncAttributeMaxDynamicSharedMemorySize, TGEMM_SMEM);
    cudaFuncSetAttribute(attn_kernel, cudaFuncAttributeMaxDynamicSharedMemorySize, ATT_SMEM);

    prep_all<<<12300, dim3(32, 8)>>>(Wq, Wk, Wv, Wo, W1, W2, bq, bk, bv,
                                     wqkv, wot, w1t, w2t, bqkv);

    ln_kernel<<<N_TOK / 8, 256>>>(x, g1, beta1, h);
    tgemm<0, __half><<<dim3(24, 64), 256, TGEMM_SMEM>>>(h, wqkv, bqkv, nullptr, qkv, 3 * EMB, EMB);
    attn_kernel<<<dim3(SEQ / 64, NH, NB), 128, ATT_SMEM>>>(qkv, yb);
    tgemm<2, float><<<dim3(8, 64), 256, TGEMM_SMEM>>>(yb, wot, bo, x, x2, EMB, EMB);
    ln_kernel<<<N_TOK / 8, 256>>>(x2, g2, beta2, h);
    tgemm<1, __half><<<dim3(32, 64), 256, TGEMM_SMEM>>>(h, w1t, b1f, nullptr, ff, FFD, EMB);
    tgemm<2, float><<<dim3(8, 64), 256, TGEMM_SMEM>>>(ff, w2t, b2, x2, out, EMB, FFD);
}